// round 1
// baseline (speedup 1.0000x reference)
#include <cuda_runtime.h>
#include <math.h>

// VIN: only batch 0 reaches the output; 150-ch conv collapses into a 2-ch 3x3
// effective conv; r-part of q is precomputed once (qr). Single CTA, whole
// 64x64 grid lives in SMEM, 19 value-iteration sweeps, then q at 64 query
// points + softmax.

#define GH 64
#define GW 64
#define PW 66              // padded row stride (1-cell zero halo)
#define NACT 8
#define NITERS 20
#define NQ 64
#define NTHREADS 512
#define NCELL (GH * GW)    // 4096
#define CELLS_PER_THREAD (NCELL / NTHREADS)  // 8

// smem layout (floats)
#define OFF_RP   0
#define OFF_VA   (OFF_RP + PW * PW)
#define OFF_VB   (OFF_VA + PW * PW)
#define OFF_QR   (OFF_VB + PW * PW)           // [8][4096]
#define OFF_WQ   (OFF_QR + NACT * NCELL)      // raw Wq [8][2][3][3] = 144
#define OFF_WEFF (OFF_WQ + 144)               // 18
#define OFF_BEFF (OFF_WEFF + 18)              // 1
#define SMEM_FLOATS (OFF_BEFF + 1)
#define SMEM_BYTES (SMEM_FLOATS * (int)sizeof(float))

__global__ __launch_bounds__(NTHREADS, 1)
void vin_kernel(const float* __restrict__ X,
                const int* __restrict__ S1,
                const int* __restrict__ S2,
                const float* __restrict__ Wh,
                const float* __restrict__ bh,
                const float* __restrict__ Wr,
                const float* __restrict__ Wq,
                float* __restrict__ out)
{
    extern __shared__ float sm[];
    float* rp   = sm + OFF_RP;    // padded reward map [66][66]
    float* vA   = sm + OFF_VA;    // padded v ping    [66][66]
    float* vB   = sm + OFF_VB;    // padded v pong    [66][66]
    float* qr   = sm + OFF_QR;    // r-part of q      [8][4096]
    float* wq   = sm + OFF_WQ;    // raw Wq           [144]
    float* weff = sm + OFF_WEFF;  // effective r conv [2][3][3]
    float* beff = sm + OFF_BEFF;

    const int t = threadIdx.x;

    // ---- init: zero padded maps, stage weights ----
    for (int i = t; i < PW * PW; i += NTHREADS) {
        rp[i] = 0.f; vA[i] = 0.f; vB[i] = 0.f;
    }
    if (t < 144) wq[t] = Wq[t];
    if (t < 18) {
        // weff[c*9 + ky*3 + kx] = sum_h Wr[h] * Wh[h, c, ky, kx]
        float s = 0.f;
        for (int h = 0; h < 150; h++) s += Wr[h] * Wh[h * 18 + t];
        weff[t] = s;
    }
    if (t == 18) {
        float s = 0.f;
        for (int h = 0; h < 150; h++) s += Wr[h] * bh[h];
        beff[0] = s;
    }
    __syncthreads();

    // ---- phase 1: reward map r (batch 0 only) ----
    {
        float we[18];
        #pragma unroll
        for (int p = 0; p < 18; p++) we[p] = weff[p];
        float b0 = beff[0];
        for (int k = 0; k < CELLS_PER_THREAD; k++) {
            int cell = t + k * NTHREADS;
            int i = cell >> 6, j = cell & 63;
            float acc = b0;
            #pragma unroll
            for (int c = 0; c < 2; c++) {
                #pragma unroll
                for (int ky = 0; ky < 3; ky++) {
                    int y = i + ky - 1;
                    if (y < 0 || y >= GH) continue;
                    #pragma unroll
                    for (int kx = 0; kx < 3; kx++) {
                        int x = j + kx - 1;
                        if (x < 0 || x >= GW) continue;
                        acc = fmaf(we[c * 9 + ky * 3 + kx],
                                   X[c * NCELL + y * GW + x], acc);
                    }
                }
            }
            rp[(i + 1) * PW + (j + 1)] = acc;
        }
    }
    __syncthreads();

    // ---- phase 2: qr[a] = conv(r, Wq[a][0]), once ----
    float w[NACT * 9];   // register-resident weights
    #pragma unroll
    for (int a = 0; a < NACT; a++)
        #pragma unroll
        for (int p = 0; p < 9; p++)
            w[a * 9 + p] = wq[a * 18 + p];           // Wq[a][0][ky][kx]

    for (int k = 0; k < CELLS_PER_THREAD; k++) {
        int cell = t + k * NTHREADS;
        int i = cell >> 6, j = cell & 63;
        float n[9];
        #pragma unroll
        for (int ky = 0; ky < 3; ky++)
            #pragma unroll
            for (int kx = 0; kx < 3; kx++)
                n[ky * 3 + kx] = rp[(i + ky) * PW + j + kx];
        #pragma unroll
        for (int a = 0; a < NACT; a++) {
            float acc = 0.f;
            #pragma unroll
            for (int p = 0; p < 9; p++)
                acc = fmaf(w[a * 9 + p], n[p], acc);
            qr[a * NCELL + cell] = acc;
        }
    }

    // switch register weights to the v-channel, held for the whole mainloop
    #pragma unroll
    for (int a = 0; a < NACT; a++)
        #pragma unroll
        for (int p = 0; p < 9; p++)
            w[a * 9 + p] = wq[a * 18 + 9 + p];       // Wq[a][1][ky][kx]
    __syncthreads();

    // ---- phase 3: 19 value-iteration sweeps (final q uses v after 19) ----
    float* cur = vA;   // v0 = 0
    float* nxt = vB;
    for (int it = 0; it < NITERS - 1; it++) {
        for (int k = 0; k < CELLS_PER_THREAD; k++) {
            int cell = t + k * NTHREADS;
            int i = cell >> 6, j = cell & 63;
            float n[9];
            #pragma unroll
            for (int ky = 0; ky < 3; ky++)
                #pragma unroll
                for (int kx = 0; kx < 3; kx++)
                    n[ky * 3 + kx] = cur[(i + ky) * PW + j + kx];
            float vmax = -INFINITY;
            #pragma unroll
            for (int a = 0; a < NACT; a++) {
                float acc = qr[a * NCELL + cell];
                #pragma unroll
                for (int p = 0; p < 9; p++)
                    acc = fmaf(w[a * 9 + p], n[p], acc);
                vmax = fmaxf(vmax, acc);
            }
            nxt[(i + 1) * PW + (j + 1)] = vmax;
        }
        __syncthreads();
        float* tmp = cur; cur = nxt; nxt = tmp;
    }

    // ---- phase 4: q at the 64 query points from v19, softmax ----
    if (t < NQ) {
        int i = S1[t];   // H index
        int j = S2[t];   // W index
        float n[9];
        #pragma unroll
        for (int ky = 0; ky < 3; ky++)
            #pragma unroll
            for (int kx = 0; kx < 3; kx++)
                n[ky * 3 + kx] = cur[(i + ky) * PW + j + kx];
        float q[NACT];
        float m = -INFINITY;
        #pragma unroll
        for (int a = 0; a < NACT; a++) {
            float acc = qr[a * NCELL + i * GW + j];
            #pragma unroll
            for (int p = 0; p < 9; p++)
                acc = fmaf(w[a * 9 + p], n[p], acc);
            q[a] = acc;
            m = fmaxf(m, acc);
        }
        float s = 0.f;
        #pragma unroll
        for (int a = 0; a < NACT; a++) {
            q[a] = expf(q[a] - m);
            s += q[a];
        }
        float inv = 1.f / s;
        #pragma unroll
        for (int a = 0; a < NACT; a++)
            out[t * NACT + a] = q[a] * inv;
    }
}

extern "C" void kernel_launch(void* const* d_in, const int* in_sizes, int n_in,
                              void* d_out, int out_size)
{
    const float* X  = (const float*)d_in[0];   // [64,2,64,64] (only batch 0 used)
    const int*   S1 = (const int*)d_in[1];     // [64]
    const int*   S2 = (const int*)d_in[2];     // [64]
    const float* Wh = (const float*)d_in[3];   // [150,2,3,3]
    const float* bh = (const float*)d_in[4];   // [150]
    const float* Wr = (const float*)d_in[5];   // [1,150,1,1]
    const float* Wq = (const float*)d_in[6];   // [8,2,3,3]
    float* out = (float*)d_out;                // [64,8]

    cudaFuncSetAttribute(vin_kernel,
                         cudaFuncAttributeMaxDynamicSharedMemorySize,
                         SMEM_BYTES);
    vin_kernel<<<1, NTHREADS, SMEM_BYTES>>>(X, S1, S2, Wh, bh, Wr, Wq, out);
}

// round 4
// speedup vs baseline: 2.6636x; 2.6636x over previous
#include <cuda_runtime.h>
#include <math.h>
#include <stdint.h>

// VIN on an 8-CTA cluster: grid split into 8-row bands, one cell per thread,
// per-iteration halo exchange via DSMEM (mapa + st.shared::cluster) and
// barrier.cluster. Only batch 0 reaches the output; the 150-ch hidden conv is
// collapsed into a 2-ch 3x3 effective conv; the r-contribution to q (qr) is
// precomputed once per CTA band.

#define GH 64
#define GW 64
#define NACT 8
#define NQ 64
#define NCL 8                 // cluster size (CTAs)
#define RPC 8                 // rows per CTA band
#define PW 66                 // padded row stride
#define LROWS (RPC + 2)       // 10 padded rows per band
#define NTH 512
#define NITERS 20
#define LCELL (RPC * GW)      // 512 cells per CTA

__device__ __forceinline__ uint32_t s2u(const void* p) {
    return (uint32_t)__cvta_generic_to_shared(p);
}
__device__ __forceinline__ void dsmem_st(uint32_t laddr, uint32_t rank, float v) {
    uint32_t raddr;
    asm volatile("mapa.shared::cluster.u32 %0, %1, %2;"
                 : "=r"(raddr) : "r"(laddr), "r"(rank));
    asm volatile("st.shared::cluster.f32 [%0], %1;"
                 :: "r"(raddr), "f"(v) : "memory");
}
__device__ __forceinline__ void cluster_sync() {
    asm volatile("barrier.cluster.arrive.aligned;" ::: "memory");
    asm volatile("barrier.cluster.wait.aligned;" ::: "memory");
}

__global__ __launch_bounds__(NTH, 1) __cluster_dims__(NCL, 1, 1)
void vin_kernel(const float* __restrict__ X,
                const int* __restrict__ S1,
                const int* __restrict__ S2,
                const float* __restrict__ Wh,
                const float* __restrict__ bh,
                const float* __restrict__ Wr,
                const float* __restrict__ Wq,
                float* __restrict__ out)
{
    __shared__ float rp[LROWS * PW];     // padded reward band
    __shared__ float vA[LROWS * PW];     // padded v ping
    __shared__ float vB[LROWS * PW];     // padded v pong
    __shared__ float qr[NACT * LCELL];   // r-part of q for own cells
    __shared__ float wqs[144];           // raw Wq [8][2][3][3]
    __shared__ float part[19 * 8];       // partial sums for weight collapse
    __shared__ float weff[19];           // [0..17] eff conv weights, [18] bias

    const int t = threadIdx.x;
    const int rank = blockIdx.x;         // cluster rank (grid == one cluster)
    const int rbase = rank * RPC;

    // ---- init: zero padded maps (halos stay 0 = zero padding), stage weights
    for (int i = t; i < LROWS * PW; i += NTH) { rp[i] = 0.f; vA[i] = 0.f; vB[i] = 0.f; }
    if (t < 144) wqs[t] = Wq[t];
    if (t < 152) {  // collapse 150-ch conv: 19 outputs x 8 partial lanes
        int p = t >> 3, c = t & 7;
        float s = 0.f;
        for (int h = c; h < 150; h += 8)
            s += Wr[h] * (p < 18 ? Wh[h * 18 + p] : bh[h]);
        part[p * 8 + c] = s;
    }
    __syncthreads();
    if (t < 19) {
        float s = 0.f;
        #pragma unroll
        for (int c = 0; c < 8; c++) s += part[t * 8 + c];
        weff[t] = s;
    }
    __syncthreads();

    // ---- phase 1: reward rows rbase-1 .. rbase+RPC (padded local rows 0..9)
    {
        float we[18];
        #pragma unroll
        for (int p = 0; p < 18; p++) we[p] = weff[p];
        const float b0 = weff[18];
        for (int idx = t; idx < LROWS * GW; idx += NTH) {
            int pr = idx >> 6, j = idx & 63;
            int gr = rbase + pr - 1;
            if (gr < 0 || gr >= GH) continue;      // halo row outside grid -> 0
            float acc = b0;
            #pragma unroll
            for (int c = 0; c < 2; c++)
                #pragma unroll
                for (int ky = 0; ky < 3; ky++) {
                    int y = gr + ky - 1;
                    if (y < 0 || y >= GH) continue;
                    #pragma unroll
                    for (int kx = 0; kx < 3; kx++) {
                        int x = j + kx - 1;
                        if (x < 0 || x >= GW) continue;
                        acc = fmaf(we[c * 9 + ky * 3 + kx],
                                   X[c * (GH * GW) + y * GW + x], acc);
                    }
                }
            rp[pr * PW + j + 1] = acc;
        }
    }
    __syncthreads();

    // ---- phase 2: qr[a] = conv(r, Wq[a][0]) for own cells, once
    float w[NACT * 9];
    #pragma unroll
    for (int a = 0; a < NACT; a++)
        #pragma unroll
        for (int p = 0; p < 9; p++)
            w[a * 9 + p] = wqs[a * 18 + p];        // Wq[a][0]

    const int li = t >> 6, j = t & 63;             // own cell: local row, col
    {
        float n[9];
        #pragma unroll
        for (int ky = 0; ky < 3; ky++)
            #pragma unroll
            for (int kx = 0; kx < 3; kx++)
                n[ky * 3 + kx] = rp[(li + ky) * PW + j + kx];
        #pragma unroll
        for (int a = 0; a < NACT; a++) {
            float acc = 0.f;
            #pragma unroll
            for (int p = 0; p < 9; p++)
                acc = fmaf(w[a * 9 + p], n[p], acc);
            qr[a * LCELL + t] = acc;
        }
    }
    // switch register weights to the v channel for the whole mainloop
    #pragma unroll
    for (int a = 0; a < NACT; a++)
        #pragma unroll
        for (int p = 0; p < 9; p++)
            w[a * 9 + p] = wqs[a * 18 + 9 + p];    // Wq[a][1]
    __syncthreads();
    cluster_sync();   // all CTAs' v buffers zero-initialized before any DSMEM write

    // ---- phase 3: 19 VI sweeps with DSMEM halo exchange
    float* cur = vA;
    float* nxt = vB;
    for (int it = 0; it < NITERS - 1; it++) {
        float n[9];
        #pragma unroll
        for (int ky = 0; ky < 3; ky++)
            #pragma unroll
            for (int kx = 0; kx < 3; kx++)
                n[ky * 3 + kx] = cur[(li + ky) * PW + j + kx];
        float vmax = -INFINITY;
        #pragma unroll
        for (int a = 0; a < NACT; a++) {
            float acc = qr[a * LCELL + t];
            #pragma unroll
            for (int p = 0; p < 9; p++)
                acc = fmaf(w[a * 9 + p], n[p], acc);
            vmax = fmaxf(vmax, acc);
        }
        nxt[(li + 1) * PW + j + 1] = vmax;
        // export border rows into neighbors' halos (same static smem layout)
        if (li == 0 && rank > 0)
            dsmem_st(s2u(&nxt[(LROWS - 1) * PW + j + 1]), rank - 1, vmax);
        if (li == RPC - 1 && rank < NCL - 1)
            dsmem_st(s2u(&nxt[j + 1]), rank + 1, vmax);
        cluster_sync();   // release our stores / acquire neighbors'
        float* tmp = cur; cur = nxt; nxt = tmp;
    }

    // ---- phase 4: q at the 64 query points from v19, softmax
    if (t < NQ) {
        int qi = S1[t], qj = S2[t];
        if (qi >= rbase && qi < rbase + RPC) {     // exactly one CTA owns each query
            int lr = qi - rbase;
            float n[9];
            #pragma unroll
            for (int ky = 0; ky < 3; ky++)
                #pragma unroll
                for (int kx = 0; kx < 3; kx++)
                    n[ky * 3 + kx] = cur[(lr + ky) * PW + qj + kx];
            float q[NACT];
            float m = -INFINITY;
            #pragma unroll
            for (int a = 0; a < NACT; a++) {
                float acc = qr[a * LCELL + lr * GW + qj];
                #pragma unroll
                for (int p = 0; p < 9; p++)
                    acc = fmaf(w[a * 9 + p], n[p], acc);
                q[a] = acc;
                m = fmaxf(m, acc);
            }
            float s = 0.f;
            #pragma unroll
            for (int a = 0; a < NACT; a++) {
                q[a] = expf(q[a] - m);
                s += q[a];
            }
            float inv = 1.f / s;
            #pragma unroll
            for (int a = 0; a < NACT; a++)
                out[t * NACT + a] = q[a] * inv;
        }
    }
}

extern "C" void kernel_launch(void* const* d_in, const int* in_sizes, int n_in,
                              void* d_out, int out_size)
{
    const float* X  = (const float*)d_in[0];   // [64,2,64,64] (batch 0 only)
    const int*   S1 = (const int*)d_in[1];     // [64]
    const int*   S2 = (const int*)d_in[2];     // [64]
    const float* Wh = (const float*)d_in[3];   // [150,2,3,3]
    const float* bh = (const float*)d_in[4];   // [150]
    const float* Wr = (const float*)d_in[5];   // [1,150,1,1]
    const float* Wq = (const float*)d_in[6];   // [8,2,3,3]
    float* out = (float*)d_out;                // [64,8]

    vin_kernel<<<NCL, NTH>>>(X, S1, S2, Wh, bh, Wr, Wq, out);
}

// round 5
// speedup vs baseline: 2.8264x; 1.0611x over previous
#include <cuda_runtime.h>
#include <math.h>
#include <stdint.h>

// VIN on an 8-CTA cluster, 256 threads/CTA, 2 adjacent cells per thread via
// fma.rn.f32x2 (FFMA2). Per-iteration halo exchange via st.shared::cluster +
// remote mbarrier.arrive.release.cluster; only border threads wait
// (try_wait.parity.acquire.cluster). Triple-buffered v makes skew-1 safe.
// Only batch 0 reaches the output; the 150-ch hidden conv collapses into a
// 2-ch 3x3 effective conv; the r-part of q (qr) is precomputed once.

#define GH 64
#define GW 64
#define NACT 8
#define NCL 8                 // cluster CTAs
#define RPC 8                 // rows per CTA band
#define PW 66                 // padded row stride
#define LROWS (RPC + 2)       // 10 padded rows per band
#define NTH 256
#define NSWEEP 19             // final q uses v after 19 updates
#define LCELL (RPC * GW)      // 512 cells per CTA

__device__ __forceinline__ uint32_t s2u(const void* p) {
    return (uint32_t)__cvta_generic_to_shared(p);
}
__device__ __forceinline__ uint64_t pack2(float x, float y) {
    uint64_t r;
    asm("mov.b64 %0, {%1, %2};" : "=l"(r) : "f"(x), "f"(y));
    return r;
}
__device__ __forceinline__ float2 unpack2(uint64_t v) {
    float2 f;
    asm("mov.b64 {%0, %1}, %2;" : "=f"(f.x), "=f"(f.y) : "l"(v));
    return f;
}
__device__ __forceinline__ uint64_t fma2(uint64_t a, uint64_t b, uint64_t c) {
    uint64_t d;
    asm("fma.rn.f32x2 %0, %1, %2, %3;" : "=l"(d) : "l"(a), "l"(b), "l"(c));
    return d;
}
__device__ __forceinline__ void cluster_sync() {
    asm volatile("barrier.cluster.arrive.aligned;" ::: "memory");
    asm volatile("barrier.cluster.wait.aligned;" ::: "memory");
}
// store 2 halo floats into neighbor's smem, then release-arrive its mbarrier
__device__ __forceinline__ void halo_out(uint32_t laddr, uint32_t rank,
                                         float v0, float v1, uint32_t lmbar) {
    asm volatile(
        "{\n\t.reg .b32 ra, rb;\n\t"
        "mapa.shared::cluster.u32 ra, %0, %1;\n\t"
        "st.shared::cluster.f32 [ra], %2;\n\t"
        "st.shared::cluster.f32 [ra+4], %3;\n\t"
        "mapa.shared::cluster.u32 rb, %4, %1;\n\t"
        "mbarrier.arrive.release.cluster.shared::cluster.b64 _, [rb];\n\t}"
        :: "r"(laddr), "r"(rank), "f"(v0), "f"(v1), "r"(lmbar) : "memory");
}
__device__ __forceinline__ void mbar_wait(uint32_t addr, uint32_t parity) {
    asm volatile(
        "{\n\t.reg .pred P;\n\t"
        "W%=:\n\t"
        "mbarrier.try_wait.parity.acquire.cluster.shared::cta.b64 P, [%0], %1, 0x989680;\n\t"
        "@P bra D%=;\n\t"
        "bra W%=;\n\t"
        "D%=:\n\t}"
        :: "r"(addr), "r"(parity) : "memory");
}

__global__ __launch_bounds__(NTH, 1) __cluster_dims__(NCL, 1, 1)
void vin_kernel(const float* __restrict__ X,
                const int* __restrict__ S1,
                const int* __restrict__ S2,
                const float* __restrict__ Wh,
                const float* __restrict__ bh,
                const float* __restrict__ Wr,
                const float* __restrict__ Wq,
                float* __restrict__ out)
{
    __shared__ float rp[LROWS * PW];           // padded reward band
    __shared__ float vA[LROWS * PW];           // v triple buffer
    __shared__ float vB[LROWS * PW];
    __shared__ float vC[LROWS * PW];
    __shared__ unsigned long long qr2[NACT * NTH];  // packed (c0,c1) r-part of q
    __shared__ float wqs[144];                 // raw Wq [8][2][3][3]
    __shared__ float part[19 * 8];             // weight-collapse partials
    __shared__ float weff[19];                 // eff conv weights + bias
    __shared__ unsigned long long mbar;        // halo mbarrier

    const int t = threadIdx.x;
    const int rank = blockIdx.x;
    const int rbase = rank * RPC;
    const int li = t >> 5;                     // local row 0..7
    const int jc = (t & 31) * 2;               // left column of the cell pair
    const uint32_t mb = s2u(&mbar);

    // ---- init: zero padded maps (halos stay 0), stage weights, mbarrier ----
    for (int i = t; i < LROWS * PW; i += NTH) {
        rp[i] = 0.f; vA[i] = 0.f; vB[i] = 0.f; vC[i] = 0.f;
    }
    if (t < 144) wqs[t] = Wq[t];
    if (t < 152) {
        int p = t >> 3, c = t & 7;
        float s = 0.f;
        for (int h = c; h < 150; h += 8)
            s += Wr[h] * (p < 18 ? Wh[h * 18 + p] : bh[h]);
        part[p * 8 + c] = s;
    }
    if (t == 0) {
        int nb = (rank == 0 || rank == NCL - 1) ? 1 : 2;
        asm volatile("mbarrier.init.shared.b64 [%0], %1;"
                     :: "r"(mb), "r"(32 * nb) : "memory");
    }
    __syncthreads();
    if (t < 19) {
        float s = 0.f;
        #pragma unroll
        for (int c = 0; c < 8; c++) s += part[t * 8 + c];
        weff[t] = s;
    }
    __syncthreads();

    // ---- phase 1: reward rows rbase-1 .. rbase+RPC (padded rows 0..9) ----
    {
        float we[18];
        #pragma unroll
        for (int p = 0; p < 18; p++) we[p] = weff[p];
        const float b0 = weff[18];
        for (int idx = t; idx < LROWS * GW; idx += NTH) {
            int pr = idx >> 6, j = idx & 63;
            int gr = rbase + pr - 1;
            if (gr < 0 || gr >= GH) continue;
            float acc = b0;
            #pragma unroll
            for (int c = 0; c < 2; c++)
                #pragma unroll
                for (int ky = 0; ky < 3; ky++) {
                    int y = gr + ky - 1;
                    if (y < 0 || y >= GH) continue;
                    #pragma unroll
                    for (int kx = 0; kx < 3; kx++) {
                        int x = j + kx - 1;
                        if (x < 0 || x >= GW) continue;
                        acc = fmaf(we[c * 9 + ky * 3 + kx],
                                   X[c * (GH * GW) + y * GW + x], acc);
                    }
                }
            rp[pr * PW + j + 1] = acc;
        }
    }
    __syncthreads();

    // ---- phase 2: qr for both own cells, once (r-channel of Wq) ----
    {
        float n[12];   // rows li..li+2, padded cols jc..jc+3
        #pragma unroll
        for (int ky = 0; ky < 3; ky++)
            #pragma unroll
            for (int kx = 0; kx < 4; kx++)
                n[ky * 4 + kx] = rp[(li + ky) * PW + jc + kx];
        #pragma unroll
        for (int a = 0; a < NACT; a++) {
            float a0 = 0.f, a1 = 0.f;
            #pragma unroll
            for (int ky = 0; ky < 3; ky++)
                #pragma unroll
                for (int kx = 0; kx < 3; kx++) {
                    float wv = wqs[a * 18 + ky * 3 + kx];
                    a0 = fmaf(wv, n[ky * 4 + kx], a0);
                    a1 = fmaf(wv, n[ky * 4 + kx + 1], a1);
                }
            qr2[a * NTH + t] = pack2(a0, a1);
        }
    }

    // packed (w,w) v-channel weights, held in registers for the whole loop
    uint64_t wp[NACT * 9];
    #pragma unroll
    for (int a = 0; a < NACT; a++)
        #pragma unroll
        for (int p = 0; p < 9; p++) {
            float wv = wqs[a * 18 + 9 + p];
            wp[a * 9 + p] = pack2(wv, wv);
        }
    __syncthreads();
    cluster_sync();   // mbar init + zeroed buffers visible cluster-wide

    // ---- phase 3: 19 VI sweeps, FFMA2, mbarrier neighbor sync ----
    float* cur = vA;
    float* nxt = vB;
    float* oth = vC;
    const bool is_top = (li == 0);
    const bool is_bot = (li == RPC - 1);
    const bool waiter = is_top || is_bot;

    for (int it = 0; it < NSWEEP; it++) {
        if (it > 0 && waiter) mbar_wait(mb, (it - 1) & 1);

        uint64_t acc[NACT];
        #pragma unroll
        for (int a = 0; a < NACT; a++)
            acc[a] = qr2[a * NTH + t];

        #pragma unroll
        for (int ky = 0; ky < 3; ky++) {
            const float* rowp = cur + (li + ky) * PW + jc;   // 8B aligned
            uint64_t a01 = *(const uint64_t*)rowp;
            uint64_t a23 = *(const uint64_t*)(rowp + 2);
            float2 f01 = unpack2(a01);
            float2 f23 = unpack2(a23);
            uint64_t p1 = pack2(f01.y, f23.x);
            #pragma unroll
            for (int a = 0; a < NACT; a++) {
                acc[a] = fma2(wp[a * 9 + ky * 3 + 0], a01, acc[a]);
                acc[a] = fma2(wp[a * 9 + ky * 3 + 1], p1,  acc[a]);
                acc[a] = fma2(wp[a * 9 + ky * 3 + 2], a23, acc[a]);
            }
        }
        float v0 = -INFINITY, v1 = -INFINITY;
        #pragma unroll
        for (int a = 0; a < NACT; a++) {
            float2 f = unpack2(acc[a]);
            v0 = fmaxf(v0, f.x);
            v1 = fmaxf(v1, f.y);
        }
        float* dst = nxt + (li + 1) * PW + jc + 1;
        dst[0] = v0;
        dst[1] = v1;

        if (it < NSWEEP - 1) {
            if (is_top && rank > 0)
                halo_out(s2u(nxt + (LROWS - 1) * PW + jc + 1), rank - 1, v0, v1, mb);
            if (is_bot && rank < NCL - 1)
                halo_out(s2u(nxt + jc + 1), rank + 1, v0, v1, mb);
        }
        __syncthreads();
        float* tmp = cur; cur = nxt; nxt = oth; oth = tmp;
    }

    // ---- phase 4: q at the 64 query points from v19, softmax ----
    if (t < 64) {
        int qi = S1[t], qj = S2[t];
        if (qi >= rbase && qi < rbase + RPC) {
            int lr = qi - rbase;
            int tq = lr * 32 + (qj >> 1);       // owning thread of cell
            int comp = qj & 1;
            float n[9];
            #pragma unroll
            for (int ky = 0; ky < 3; ky++)
                #pragma unroll
                for (int kx = 0; kx < 3; kx++)
                    n[ky * 3 + kx] = cur[(lr + ky) * PW + qj + kx];
            float q[NACT];
            float m = -INFINITY;
            #pragma unroll
            for (int a = 0; a < NACT; a++) {
                float2 qv = unpack2(qr2[a * NTH + tq]);
                float acc = comp ? qv.y : qv.x;
                #pragma unroll
                for (int p = 0; p < 9; p++)
                    acc = fmaf(wqs[a * 18 + 9 + p], n[p], acc);
                q[a] = acc;
                m = fmaxf(m, acc);
            }
            float s = 0.f;
            #pragma unroll
            for (int a = 0; a < NACT; a++) {
                q[a] = expf(q[a] - m);
                s += q[a];
            }
            float inv = 1.f / s;
            #pragma unroll
            for (int a = 0; a < NACT; a++)
                out[t * NACT + a] = q[a] * inv;
        }
    }
}

extern "C" void kernel_launch(void* const* d_in, const int* in_sizes, int n_in,
                              void* d_out, int out_size)
{
    const float* X  = (const float*)d_in[0];   // [64,2,64,64] (batch 0 only)
    const int*   S1 = (const int*)d_in[1];     // [64]
    const int*   S2 = (const int*)d_in[2];     // [64]
    const float* Wh = (const float*)d_in[3];   // [150,2,3,3]
    const float* bh = (const float*)d_in[4];   // [150]
    const float* Wr = (const float*)d_in[5];   // [1,150,1,1]
    const float* Wq = (const float*)d_in[6];   // [8,2,3,3]
    float* out = (float*)d_out;                // [64,8]

    vin_kernel<<<NCL, NTH>>>(X, S1, S2, Wh, bh, Wr, Wq, out);
}